// round 15
// baseline (speedup 1.0000x reference)
#include <cuda_runtime.h>
#include <cuda_fp16.h>
#include <cstdint>
#include <math.h>

#define BD 2
#define VD 65536
#define CIND 128
#define COUTD 256
#define TDIMD 512
#define EPSF 1e-5f

// ================= scratch (device globals) =================
__device__ __half g_hn1h[(size_t)BD * VD * CIND];
__device__ __half g_hn2h[(size_t)BD * VD * COUTD];
__device__ __half g_xh[(size_t)BD * VD * CIND];
__device__ __half g_h16[(size_t)BD * VD * COUTD];   // conv1 output, fp16
__device__ __half g_w1h[COUTD * 9 * CIND];
__device__ __half g_w2h[COUTD * 9 * COUTD];
__device__ __half g_wsh[COUTD * CIND];
__device__ float g_sum1[64], g_sumsq1[64];
__device__ float g_sum2[64], g_sumsq2[64];
__device__ float g_t[BD * COUTD];

__device__ __forceinline__ float silu_f(float z) { return z / (1.f + __expf(-z)); }
__device__ __forceinline__ uint32_t smem_to_u32(const void* p) {
    uint32_t a;
    asm("{ .reg .u64 t; cvta.to.shared.u64 t, %1; cvt.u32.u64 %0, t; }" : "=r"(a) : "l"(p));
    return a;
}

#define LDSM4(r0, r1, r2, r3, addr) \
    asm volatile("ldmatrix.sync.aligned.m8n8.x4.shared.b16 {%0,%1,%2,%3}, [%4];" \
        : "=r"(r0), "=r"(r1), "=r"(r2), "=r"(r3) : "r"(addr))

#define MMA_F16(d, a, b) \
    asm volatile("mma.sync.aligned.m16n8k16.row.col.f32.f16.f16.f32 " \
        "{%0,%1,%2,%3},{%4,%5,%6,%7},{%8,%9},{%0,%1,%2,%3};" \
        : "+f"((d)[0]), "+f"((d)[1]), "+f"((d)[2]), "+f"((d)[3]) \
        : "r"((a)[0]), "r"((a)[1]), "r"((a)[2]), "r"((a)[3]), "r"((b)[0]), "r"((b)[1]))

#define CP_ASYNC16(dst, src) \
    asm volatile("cp.async.cg.shared.global [%0], [%1], 16;" :: "r"(dst), "l"(src))
#define CP_COMMIT() asm volatile("cp.async.commit_group;")
#define CP_WAIT1()  asm volatile("cp.async.wait_group 1;")
#define CP_WAIT0()  asm volatile("cp.async.wait_group 0;")

// ================= prep: zero stats + t vector + weight fp16 =================
__global__ __launch_bounds__(256) void prep_kernel(const float* __restrict__ t_emb,
                                                   const float* __restrict__ wt,
                                                   const float* __restrict__ bt,
                                                   const float* __restrict__ w1,
                                                   const float* __restrict__ w2,
                                                   const float* __restrict__ ws) {
    int bi = blockIdx.x;
    int tid = threadIdx.x;
    if (bi < 16) {
        __shared__ float te[TDIMD];
        int b = bi >> 3;
        int ob = (bi & 7) * 32;
        for (int i = tid; i < TDIMD; i += 256) te[i] = silu_f(t_emb[b * TDIMD + i]);
        __syncthreads();
        int o = ob + (tid >> 3);
        int l8 = tid & 7;
        const float* wrow = &wt[(size_t)o * TDIMD];
        float acc = 0.f;
        #pragma unroll
        for (int j = 0; j < 16; ++j) {
            int k = (l8 + j * 8) * 4;
            float4 w4 = *reinterpret_cast<const float4*>(&wrow[k]);
            acc += te[k] * w4.x + te[k+1] * w4.y + te[k+2] * w4.z + te[k+3] * w4.w;
        }
        #pragma unroll
        for (int off = 4; off; off >>= 1)
            acc += __shfl_down_sync(0xFFFFFFFFu, acc, off);
        if (l8 == 0) g_t[b * COUTD + o] = acc + bt[o];
    } else if (bi == 16) {
        if (tid < 64) { g_sum1[tid] = 0.f; g_sumsq1[tid] = 0.f; g_sum2[tid] = 0.f; g_sumsq2[tid] = 0.f; }
    } else {
        int idx = (bi - 17) * 256 + tid;
        const int N1 = COUTD * 9 * CIND;
        const int N2 = COUTD * 9 * COUTD;
        const int NS = COUTD * CIND;
        if (idx < N1)                 g_w1h[idx] = __float2half_rn(w1[idx]);
        else if (idx < N1 + N2)       { int j = idx - N1; g_w2h[j] = __float2half_rn(w2[j]); }
        else if (idx < N1 + N2 + NS)  { int j = idx - N1 - N2; g_wsh[j] = __float2half_rn(ws[j]); }
    }
}

__global__ __launch_bounds__(256) void gn1_stats_kernel(const float* __restrict__ x) {
    int rowStart = blockIdx.x * 128;
    int b = rowStart >> 16;
    int tid = threadIdx.x;
    int g = tid & 31, sub = tid >> 5;
    float s = 0.f, ss = 0.f;
    for (int r = sub; r < 128; r += 8) {
        float4 v = *reinterpret_cast<const float4*>(&x[(size_t)(rowStart + r) * CIND + g * 4]);
        s  += v.x + v.y + v.z + v.w;
        ss += v.x * v.x + v.y * v.y + v.z * v.z + v.w * v.w;
    }
    __shared__ float sh[32], shs[32];
    if (tid < 32) { sh[tid] = 0.f; shs[tid] = 0.f; }
    __syncthreads();
    atomicAdd(&sh[g], s); atomicAdd(&shs[g], ss);
    __syncthreads();
    if (tid < 32) { atomicAdd(&g_sum1[b * 32 + tid], sh[tid]); atomicAdd(&g_sumsq1[b * 32 + tid], shs[tid]); }
}

// hn1 = fp16(silu(gn1(x))) ; x -> fp16 ; finalize1 inlined
__global__ __launch_bounds__(256) void hn1split_kernel(const float* __restrict__ x,
                                                       const float* __restrict__ w,
                                                       const float* __restrict__ bb) {
    int idx = blockIdx.x * 256 + threadIdx.x;
    int g = idx & 31;
    int row = idx >> 5;
    int b = row >> 16;
    const float inv = 1.f / (float)(VD * 4);
    float m = g_sum1[b * 32 + g] * inv;
    float rs = rsqrtf(g_sumsq1[b * 32 + g] * inv - m * m + EPSF);
    float4 xv = *reinterpret_cast<const float4*>(&x[(size_t)idx * 4]);
    int c0 = g * 4;
    float4 wv = *reinterpret_cast<const float4*>(&w[c0]);
    float4 bv = *reinterpret_cast<const float4*>(&bb[c0]);
    float o0 = silu_f((xv.x - m) * rs * wv.x + bv.x);
    float o1 = silu_f((xv.y - m) * rs * wv.y + bv.y);
    float o2 = silu_f((xv.z - m) * rs * wv.z + bv.z);
    float o3 = silu_f((xv.w - m) * rs * wv.w + bv.w);
    union { __half b[4]; uint2 u; } H, XH;
    H.b[0] = __float2half_rn(o0); H.b[1] = __float2half_rn(o1);
    H.b[2] = __float2half_rn(o2); H.b[3] = __float2half_rn(o3);
    XH.b[0] = __float2half_rn(xv.x); XH.b[1] = __float2half_rn(xv.y);
    XH.b[2] = __float2half_rn(xv.z); XH.b[3] = __float2half_rn(xv.w);
    *reinterpret_cast<uint2*>(&g_hn1h[(size_t)idx * 4]) = H.u;
    *reinterpret_cast<uint2*>(&g_xh[(size_t)idx * 4]) = XH.u;
}

// hn2 = fp16(silu(gn2(h))) ; h read as fp16 ; finalize2 inlined
__global__ __launch_bounds__(256) void hn2split_kernel(const float* __restrict__ w,
                                                       const float* __restrict__ bb) {
    int idx = blockIdx.x * 256 + threadIdx.x;
    int c4 = idx & 63;
    int g = c4 >> 1;
    int row = idx >> 6;
    int b = row >> 16;
    const float inv = 1.f / (float)(VD * 8);
    float m = g_sum2[b * 32 + g] * inv;
    float rs = rsqrtf(g_sumsq2[b * 32 + g] * inv - m * m + EPSF);
    union { __half h[4]; uint2 u; } V;
    V.u = *reinterpret_cast<const uint2*>(&g_h16[(size_t)idx * 4]);
    float v0 = __half2float(V.h[0]);
    float v1 = __half2float(V.h[1]);
    float v2 = __half2float(V.h[2]);
    float v3 = __half2float(V.h[3]);
    int c0 = c4 * 4;
    float4 wv = *reinterpret_cast<const float4*>(&w[c0]);
    float4 bv = *reinterpret_cast<const float4*>(&bb[c0]);
    float o0 = silu_f((v0 - m) * rs * wv.x + bv.x);
    float o1 = silu_f((v1 - m) * rs * wv.y + bv.y);
    float o2 = silu_f((v2 - m) * rs * wv.z + bv.z);
    float o3 = silu_f((v3 - m) * rs * wv.w + bv.w);
    union { __half b[4]; uint2 u; } H;
    H.b[0] = __float2half_rn(o0); H.b[1] = __float2half_rn(o1);
    H.b[2] = __float2half_rn(o2); H.b[3] = __float2half_rn(o3);
    *reinterpret_cast<uint2*>(&g_hn2h[(size_t)idx * 4]) = H.u;
}

// ================= mma.sync gather-GEMM, fp16, K-chunk 64, 3 CTAs/SM =================
// CTA 64x128 tile, 8 warps (2m x 4n), warp tile 32x32, K-chunk 64.
// 3-stage ring, one barrier per chunk. 3 CTAs/SM for latency hiding.
// smem rows: 64 fp16 = 128B, 8 atoms of 16B, XOR swizzle atom^(row&7).
#define SM_NIDX 0
#define SM_SG   2304
#define SM_SQ   2368
#define SM_BUF  2432
#define BUFSZ   24576
#define OFF_A   0
#define OFF_B   8192
#define SMEMSZ  (SM_BUF + 3 * BUFSZ)   // 76160

template<bool CONV2>
__device__ __forceinline__ void issue_load(int c, int tid, int rowStart, int colB,
                                           size_t bbase, const int* s_nidx,
                                           uint32_t bufbase) {
    const int KW = CONV2 ? 2304 : 1152;
    // ---- A: 64 rows x 128B, 2 atoms per thread (r = tid>>2, q = tid&3) ----
    {
        int r = tid >> 2, q = tid & 3;
        const __half* pa;
        if (!CONV2) {
            int n = c >> 1, koff = (c & 1) << 6;
            pa = g_hn1h + (bbase + (size_t)s_nidx[n * 64 + r]) * CIND + koff;
        } else if (c < 36) {
            int n = c >> 2, koff = (c & 3) << 6;
            pa = g_hn2h + (bbase + (size_t)s_nidx[n * 64 + r]) * COUTD + koff;
        } else {
            pa = g_xh + (size_t)(rowStart + r) * CIND + ((c - 36) << 6);
        }
        uint32_t arow = bufbase + OFF_A + r * 128;
        int r7 = r & 7;
        #pragma unroll
        for (int j = 0; j < 2; ++j) {
            int a = q * 2 + j;
            CP_ASYNC16(arow + (uint32_t)((a ^ r7) << 4), (const char*)pa + a * 16);
        }
    }
    // ---- B: 128 rows x 128B, 4 atoms per thread (r = tid>>1, h = tid&1) ----
    {
        int r = tid >> 1, h = tid & 1;
        const __half* pw;
        if (!CONV2)        pw = g_w1h + (size_t)(colB + r) * KW + c * 64;
        else if (c < 36)   pw = g_w2h + (size_t)(colB + r) * KW + c * 64;
        else               pw = g_wsh + (size_t)(colB + r) * CIND + ((c - 36) << 6);
        uint32_t brow = bufbase + OFF_B + r * 128;
        int r7 = r & 7;
        #pragma unroll
        for (int j = 0; j < 4; ++j) {
            int a = h * 4 + j;
            CP_ASYNC16(brow + (uint32_t)((a ^ r7) << 4), (const char*)pw + a * 16);
        }
    }
}

template<bool CONV2>
__global__ __launch_bounds__(256, 3) void conv_mma_kernel(
    const float* __restrict__ bias,
    const float* __restrict__ bias2,   // bs for conv2; g_t used for conv1
    const int* __restrict__ neigh,
    float* __restrict__ outp)          // d_out for conv2; g_h16 for conv1
{
    extern __shared__ __align__(16) char smem[];
    const int NC = CONV2 ? 38 : 18;
    int tid = threadIdx.x;
    int lane = tid & 31, warp = tid >> 5;
    int wm = warp & 1, wn = warp >> 1;
    int rowStart = blockIdx.x * 64;
    int colB = blockIdx.y * 128;
    int b = rowStart >> 16;
    int v0 = rowStart & (VD - 1);
    size_t bbase = (size_t)b << 16;

    int* s_nidx = (int*)(smem + SM_NIDX);
    float* sg = (float*)(smem + SM_SG);
    float* sq = (float*)(smem + SM_SQ);
    for (int i = tid; i < 9 * 64; i += 256)
        s_nidx[i] = neigh[(v0 + (i & 63)) * 9 + (i >> 6)];
    if (!CONV2 && tid < 16) { sg[tid] = 0.f; sq[tid] = 0.f; }
    __syncthreads();   // s_nidx visible before any issue_load

    uint32_t sb32 = smem_to_u32(smem);

    issue_load<CONV2>(0, tid, rowStart, colB, bbase, s_nidx, sb32 + SM_BUF);
    CP_COMMIT();
    issue_load<CONV2>(1, tid, rowStart, colB, bbase, s_nidx, sb32 + SM_BUF + BUFSZ);
    CP_COMMIT();

    // ldmatrix addressing (all fragment rows have row&7 == lane&7)
    int sx = lane & 7;
    int abit = lane >> 4;
    int bbit = (lane >> 3) & 1;
    uint32_t arow0 = (uint32_t)(wm * 32 + (lane & 15)) * 128;
    uint32_t brow0 = (uint32_t)(wn * 32 + ((lane >> 4) << 3) + sx) * 128;

    float acc[2][4][4];
    #pragma unroll
    for (int i = 0; i < 2; ++i)
        #pragma unroll
        for (int j = 0; j < 4; ++j)
            #pragma unroll
            for (int k = 0; k < 4; ++k) acc[i][j][k] = 0.f;

    int st = 0;                 // = c % 3
    int st2 = 2;                // = (c + 2) % 3
    for (int c = 0; c < NC; ++c) {
        if (c + 2 < NC) { CP_WAIT1(); } else { CP_WAIT0(); }
        __syncthreads();        // stage c ready; stage st2 reads done by all

        if (c + 2 < NC) {
            issue_load<CONV2>(c + 2, tid, rowStart, colB, bbase, s_nidx,
                              sb32 + SM_BUF + st2 * BUFSZ);
            CP_COMMIT();
        }

        uint32_t baseA = sb32 + SM_BUF + st * BUFSZ + OFF_A;
        uint32_t baseB = sb32 + SM_BUF + st * BUFSZ + OFF_B;
        #pragma unroll
        for (int s = 0; s < 4; ++s) {
            uint32_t kaA = (uint32_t)(((2 * s + abit) ^ sx) << 4);
            uint32_t kaB = (uint32_t)(((2 * s + bbit) ^ sx) << 4);
            uint32_t af[2][4], bhf[4][2];
            #pragma unroll
            for (int i = 0; i < 2; ++i)
                LDSM4(af[i][0], af[i][1], af[i][2], af[i][3],
                      baseA + arow0 + (uint32_t)(i * 2048) + kaA);
            #pragma unroll
            for (int p = 0; p < 2; ++p) {
                uint32_t t0, t1, t2, t3;
                LDSM4(t0, t1, t2, t3, baseB + brow0 + (uint32_t)(p * 2048) + kaB);
                bhf[2*p][0] = t0; bhf[2*p][1] = t1; bhf[2*p+1][0] = t2; bhf[2*p+1][1] = t3;
            }
            #pragma unroll
            for (int i = 0; i < 2; ++i)
                #pragma unroll
                for (int j = 0; j < 4; ++j) MMA_F16(acc[i][j], af[i], bhf[j]);
        }
        st  = (st  == 2) ? 0 : st  + 1;
        st2 = (st2 == 2) ? 0 : st2 + 1;
    }

    // ---- epilogue ----
    int lr = lane >> 2;
    int lc = (lane & 3) * 2;
    #pragma unroll
    for (int j = 0; j < 4; ++j) {
        int col = colB + wn * 32 + j * 8 + lc;
        float ax = bias[col]     + (CONV2 ? bias2[col]     : g_t[b * COUTD + col]);
        float ay = bias[col + 1] + (CONV2 ? bias2[col + 1] : g_t[b * COUTD + col + 1]);
        float sj = 0.f, qj = 0.f;
        #pragma unroll
        for (int i = 0; i < 2; ++i) {
            int r0 = rowStart + wm * 32 + i * 16 + lr;
            float o0 = acc[i][j][0] + ax, o1 = acc[i][j][1] + ay;
            float o2 = acc[i][j][2] + ax, o3 = acc[i][j][3] + ay;
            if (CONV2) {
                float2 v0 = {o0, o1}, v1 = {o2, o3};
                *reinterpret_cast<float2*>(&outp[(size_t)r0 * COUTD + col]) = v0;
                *reinterpret_cast<float2*>(&outp[(size_t)(r0 + 8) * COUTD + col]) = v1;
            } else {
                __half2 p0 = __floats2half2_rn(o0, o1);
                __half2 p1 = __floats2half2_rn(o2, o3);
                *reinterpret_cast<__half2*>(&g_h16[(size_t)r0 * COUTD + col]) = p0;
                *reinterpret_cast<__half2*>(&g_h16[(size_t)(r0 + 8) * COUTD + col]) = p1;
                sj += o0 + o1 + o2 + o3;
                qj += o0 * o0 + o1 * o1 + o2 * o2 + o3 * o3;
            }
        }
        if (!CONV2) {
            #pragma unroll
            for (int off = 16; off; off >>= 1) {
                sj += __shfl_xor_sync(0xFFFFFFFFu, sj, off);
                qj += __shfl_xor_sync(0xFFFFFFFFu, qj, off);
            }
            if (lane == 0) {
                atomicAdd(&sg[wn * 4 + j], sj);
                atomicAdd(&sq[wn * 4 + j], qj);
            }
        }
    }
    if (!CONV2) {
        __syncthreads();
        if (tid < 16) {
            int gidx = b * 32 + (colB >> 3) + tid;
            atomicAdd(&g_sum2[gidx], sg[tid]);
            atomicAdd(&g_sumsq2[gidx], sq[tid]);
        }
    }
}

// ================= launch =================
extern "C" void kernel_launch(void* const* d_in, const int* in_sizes, int n_in,
                              void* d_out, int out_size) {
    const float* x      = (const float*)d_in[0];
    const float* t_emb  = (const float*)d_in[1];
    const int*   neigh  = (const int*)d_in[2];
    const float* gn1_w  = (const float*)d_in[3];
    const float* gn1_b  = (const float*)d_in[4];
    const float* w1     = (const float*)d_in[5];
    const float* b1     = (const float*)d_in[6];
    const float* wt     = (const float*)d_in[7];
    const float* bt     = (const float*)d_in[8];
    const float* gn2_w  = (const float*)d_in[9];
    const float* gn2_b  = (const float*)d_in[10];
    const float* w2     = (const float*)d_in[11];
    const float* b2     = (const float*)d_in[12];
    const float* ws     = (const float*)d_in[13];
    const float* bs     = (const float*)d_in[14];
    float* out = (float*)d_out;

    static bool attr_set = false;
    if (!attr_set) {
        cudaFuncSetAttribute(conv_mma_kernel<false>, cudaFuncAttributeMaxDynamicSharedMemorySize, SMEMSZ);
        cudaFuncSetAttribute(conv_mma_kernel<true>,  cudaFuncAttributeMaxDynamicSharedMemorySize, SMEMSZ);
        attr_set = true;
    }

    prep_kernel<<<3601, 256>>>(t_emb, wt, bt, w1, w2, ws);
    gn1_stats_kernel<<<1024, 256>>>(x);
    hn1split_kernel<<<16384, 256>>>(x, gn1_w, gn1_b);
    conv_mma_kernel<false><<<dim3(2048, 2), 256, SMEMSZ>>>(b1, nullptr, neigh, nullptr);
    hn2split_kernel<<<32768, 256>>>(gn2_w, gn2_b);
    conv_mma_kernel<true><<<dim3(2048, 2), 256, SMEMSZ>>>(b2, bs, neigh, out);
}

// round 16
// speedup vs baseline: 1.0693x; 1.0693x over previous
#include <cuda_runtime.h>
#include <cuda_fp16.h>
#include <cstdint>
#include <math.h>

#define BD 2
#define VD 65536
#define CIND 128
#define COUTD 256
#define TDIMD 512
#define EPSF 1e-5f

// ================= scratch (device globals) =================
__device__ __half g_hn1h[(size_t)BD * VD * CIND];
__device__ __half g_hn2h[(size_t)BD * VD * COUTD];
__device__ __half g_xh[(size_t)BD * VD * CIND];
__device__ __half g_h16[(size_t)BD * VD * COUTD];   // conv1 output, fp16
__device__ __half g_w1h[COUTD * 9 * CIND];
__device__ __half g_w2h[COUTD * 9 * COUTD];
__device__ __half g_wsh[COUTD * CIND];
__device__ float g_sum1[64], g_sumsq1[64];
__device__ float g_sum2[64], g_sumsq2[64];
__device__ float g_t[BD * COUTD];

__device__ __forceinline__ float silu_f(float z) { return z / (1.f + __expf(-z)); }
__device__ __forceinline__ uint32_t smem_to_u32(const void* p) {
    uint32_t a;
    asm("{ .reg .u64 t; cvta.to.shared.u64 t, %1; cvt.u32.u64 %0, t; }" : "=r"(a) : "l"(p));
    return a;
}

#define LDSM4(r0, r1, r2, r3, addr) \
    asm volatile("ldmatrix.sync.aligned.m8n8.x4.shared.b16 {%0,%1,%2,%3}, [%4];" \
        : "=r"(r0), "=r"(r1), "=r"(r2), "=r"(r3) : "r"(addr))

#define MMA_F16(d, a, b) \
    asm volatile("mma.sync.aligned.m16n8k16.row.col.f32.f16.f16.f32 " \
        "{%0,%1,%2,%3},{%4,%5,%6,%7},{%8,%9},{%0,%1,%2,%3};" \
        : "+f"((d)[0]), "+f"((d)[1]), "+f"((d)[2]), "+f"((d)[3]) \
        : "r"((a)[0]), "r"((a)[1]), "r"((a)[2]), "r"((a)[3]), "r"((b)[0]), "r"((b)[1]))

#define CP_ASYNC16(dst, src) \
    asm volatile("cp.async.cg.shared.global [%0], [%1], 16;" :: "r"(dst), "l"(src))
#define CP_COMMIT() asm volatile("cp.async.commit_group;")
#define CP_WAIT1()  asm volatile("cp.async.wait_group 1;")
#define CP_WAIT0()  asm volatile("cp.async.wait_group 0;")

// ================= prep: zero stats + t vector + weight fp16 =================
__global__ __launch_bounds__(256) void prep_kernel(const float* __restrict__ t_emb,
                                                   const float* __restrict__ wt,
                                                   const float* __restrict__ bt,
                                                   const float* __restrict__ w1,
                                                   const float* __restrict__ w2,
                                                   const float* __restrict__ ws) {
    int bi = blockIdx.x;
    int tid = threadIdx.x;
    if (bi < 16) {
        __shared__ float te[TDIMD];
        int b = bi >> 3;
        int ob = (bi & 7) * 32;
        for (int i = tid; i < TDIMD; i += 256) te[i] = silu_f(t_emb[b * TDIMD + i]);
        __syncthreads();
        int o = ob + (tid >> 3);
        int l8 = tid & 7;
        const float* wrow = &wt[(size_t)o * TDIMD];
        float acc = 0.f;
        #pragma unroll
        for (int j = 0; j < 16; ++j) {
            int k = (l8 + j * 8) * 4;
            float4 w4 = *reinterpret_cast<const float4*>(&wrow[k]);
            acc += te[k] * w4.x + te[k+1] * w4.y + te[k+2] * w4.z + te[k+3] * w4.w;
        }
        #pragma unroll
        for (int off = 4; off; off >>= 1)
            acc += __shfl_down_sync(0xFFFFFFFFu, acc, off);
        if (l8 == 0) g_t[b * COUTD + o] = acc + bt[o];
    } else if (bi == 16) {
        if (tid < 64) { g_sum1[tid] = 0.f; g_sumsq1[tid] = 0.f; g_sum2[tid] = 0.f; g_sumsq2[tid] = 0.f; }
    } else {
        int idx = (bi - 17) * 256 + tid;
        const int N1 = COUTD * 9 * CIND;
        const int N2 = COUTD * 9 * COUTD;
        const int NS = COUTD * CIND;
        if (idx < N1)                 g_w1h[idx] = __float2half_rn(w1[idx]);
        else if (idx < N1 + N2)       { int j = idx - N1; g_w2h[j] = __float2half_rn(w2[j]); }
        else if (idx < N1 + N2 + NS)  { int j = idx - N1 - N2; g_wsh[j] = __float2half_rn(ws[j]); }
    }
}

__global__ __launch_bounds__(256) void gn1_stats_kernel(const float* __restrict__ x) {
    int rowStart = blockIdx.x * 128;
    int b = rowStart >> 16;
    int tid = threadIdx.x;
    int g = tid & 31, sub = tid >> 5;
    float s = 0.f, ss = 0.f;
    for (int r = sub; r < 128; r += 8) {
        float4 v = *reinterpret_cast<const float4*>(&x[(size_t)(rowStart + r) * CIND + g * 4]);
        s  += v.x + v.y + v.z + v.w;
        ss += v.x * v.x + v.y * v.y + v.z * v.z + v.w * v.w;
    }
    __shared__ float sh[32], shs[32];
    if (tid < 32) { sh[tid] = 0.f; shs[tid] = 0.f; }
    __syncthreads();
    atomicAdd(&sh[g], s); atomicAdd(&shs[g], ss);
    __syncthreads();
    if (tid < 32) { atomicAdd(&g_sum1[b * 32 + tid], sh[tid]); atomicAdd(&g_sumsq1[b * 32 + tid], shs[tid]); }
}

// hn1 = fp16(silu(gn1(x))) ; x -> fp16 ; finalize1 inlined
__global__ __launch_bounds__(256) void hn1split_kernel(const float* __restrict__ x,
                                                       const float* __restrict__ w,
                                                       const float* __restrict__ bb) {
    int idx = blockIdx.x * 256 + threadIdx.x;
    int g = idx & 31;
    int row = idx >> 5;
    int b = row >> 16;
    const float inv = 1.f / (float)(VD * 4);
    float m = g_sum1[b * 32 + g] * inv;
    float rs = rsqrtf(g_sumsq1[b * 32 + g] * inv - m * m + EPSF);
    float4 xv = *reinterpret_cast<const float4*>(&x[(size_t)idx * 4]);
    int c0 = g * 4;
    float4 wv = *reinterpret_cast<const float4*>(&w[c0]);
    float4 bv = *reinterpret_cast<const float4*>(&bb[c0]);
    float o0 = silu_f((xv.x - m) * rs * wv.x + bv.x);
    float o1 = silu_f((xv.y - m) * rs * wv.y + bv.y);
    float o2 = silu_f((xv.z - m) * rs * wv.z + bv.z);
    float o3 = silu_f((xv.w - m) * rs * wv.w + bv.w);
    union { __half b[4]; uint2 u; } H, XH;
    H.b[0] = __float2half_rn(o0); H.b[1] = __float2half_rn(o1);
    H.b[2] = __float2half_rn(o2); H.b[3] = __float2half_rn(o3);
    XH.b[0] = __float2half_rn(xv.x); XH.b[1] = __float2half_rn(xv.y);
    XH.b[2] = __float2half_rn(xv.z); XH.b[3] = __float2half_rn(xv.w);
    *reinterpret_cast<uint2*>(&g_hn1h[(size_t)idx * 4]) = H.u;
    *reinterpret_cast<uint2*>(&g_xh[(size_t)idx * 4]) = XH.u;
}

// hn2 = fp16(silu(gn2(h))) ; h read as fp16 ; finalize2 inlined
__global__ __launch_bounds__(256) void hn2split_kernel(const float* __restrict__ w,
                                                       const float* __restrict__ bb) {
    int idx = blockIdx.x * 256 + threadIdx.x;
    int c4 = idx & 63;
    int g = c4 >> 1;
    int row = idx >> 6;
    int b = row >> 16;
    const float inv = 1.f / (float)(VD * 8);
    float m = g_sum2[b * 32 + g] * inv;
    float rs = rsqrtf(g_sumsq2[b * 32 + g] * inv - m * m + EPSF);
    union { __half h[4]; uint2 u; } V;
    V.u = *reinterpret_cast<const uint2*>(&g_h16[(size_t)idx * 4]);
    float v0 = __half2float(V.h[0]);
    float v1 = __half2float(V.h[1]);
    float v2 = __half2float(V.h[2]);
    float v3 = __half2float(V.h[3]);
    int c0 = c4 * 4;
    float4 wv = *reinterpret_cast<const float4*>(&w[c0]);
    float4 bv = *reinterpret_cast<const float4*>(&bb[c0]);
    float o0 = silu_f((v0 - m) * rs * wv.x + bv.x);
    float o1 = silu_f((v1 - m) * rs * wv.y + bv.y);
    float o2 = silu_f((v2 - m) * rs * wv.z + bv.z);
    float o3 = silu_f((v3 - m) * rs * wv.w + bv.w);
    union { __half b[4]; uint2 u; } H;
    H.b[0] = __float2half_rn(o0); H.b[1] = __float2half_rn(o1);
    H.b[2] = __float2half_rn(o2); H.b[3] = __float2half_rn(o3);
    *reinterpret_cast<uint2*>(&g_hn2h[(size_t)idx * 4]) = H.u;
}

// ================= mma.sync gather-GEMM, fp16, K-chunk 64, 3-stage (R14) =================
// CTA 128x128 tile, 8 warps (2m x 4n), warp tile 64x32, K-chunk 64.
// ONE barrier per chunk. Loop-invariant addresses hoisted.
// smem rows: 64 fp16 = 128B, 8 atoms of 16B, XOR swizzle atom^(row&7).
#define SM_NIDX 0
#define SM_SG   4608
#define SM_SQ   4672
#define SM_BUF  4864
#define BUFSZ   32768
#define OFF_A   0
#define OFF_B   16384
#define SMEMSZ  (SM_BUF + 3 * BUFSZ)   // 103168

template<bool CONV2>
__global__ __launch_bounds__(256, 2) void conv_mma_kernel(
    const float* __restrict__ bias,
    const float* __restrict__ bias2,   // bs for conv2; g_t used for conv1
    const int* __restrict__ neigh,
    float* __restrict__ outp)          // d_out for conv2; g_h16 for conv1
{
    extern __shared__ __align__(16) char smem[];
    const int NC = CONV2 ? 38 : 18;
    const int KW = CONV2 ? 2304 : 1152;
    const int AROW = CONV2 ? COUTD : CIND;
    const __half* __restrict__ Abase = CONV2 ? g_hn2h : g_hn1h;
    const __half* __restrict__ Wbase = CONV2 ? g_w2h : g_w1h;
    const int NWCH = CONV2 ? 36 : 18;   // chunks covered by main weights

    int tid = threadIdx.x;
    int lane = tid & 31, warp = tid >> 5;
    int wm = warp & 1, wn = warp >> 1;
    int rowStart = blockIdx.x * 128;
    int colB = blockIdx.y * 128;
    int b = rowStart >> 16;
    int v0 = rowStart & (VD - 1);
    size_t bbase = (size_t)b << 16;

    int* s_nidx = (int*)(smem + SM_NIDX);
    float* sg = (float*)(smem + SM_SG);
    float* sq = (float*)(smem + SM_SQ);
    for (int i = tid; i < 9 * 128; i += 256)
        s_nidx[i] = neigh[(v0 + (i & 127)) * 9 + (i >> 7)];
    if (!CONV2 && tid < 16) { sg[tid] = 0.f; sq[tid] = 0.f; }
    __syncthreads();   // s_nidx visible before any issue_load

    uint32_t sb32 = smem_to_u32(smem);

    // ---- hoisted load-side addressing ----
    int lr_ = tid >> 1, lh = tid & 1;
    int r7 = lr_ & 7;
    // weight row pointers (element offsets within row hoisted)
    const __half* wrowMain = Wbase + (size_t)(colB + lr_) * KW + lh * 32;
    const __half* wrowSC   = g_wsh + (size_t)(colB + lr_) * CIND + lh * 32;
    // A shortcut row pointer
    const __half* xrow = g_xh + (size_t)(rowStart + lr_) * CIND + lh * 32;
    // smem store offsets (swizzled), relative to stage base
    uint32_t soA[4], soB[4];
    #pragma unroll
    for (int j = 0; j < 4; ++j) {
        uint32_t so = (uint32_t)(((lh * 4 + j) ^ r7) << 4);
        soA[j] = OFF_A + (uint32_t)lr_ * 128 + so;
        soB[j] = OFF_B + (uint32_t)lr_ * 128 + so;
    }

    // ---- issue_load as a lambda over chunk index ----
    auto issue_load = [&](int c, uint32_t bufbase) {
        const __half *pa, *pw;
        if (!CONV2) {
            int n = c >> 1, koff = (c & 1) << 6;
            pa = Abase + (bbase + (size_t)s_nidx[n * 128 + lr_]) * AROW + koff + lh * 32;
            pw = wrowMain + c * 64;
        } else if (c < NWCH) {
            int n = c >> 2, koff = (c & 3) << 6;
            pa = Abase + (bbase + (size_t)s_nidx[n * 128 + lr_]) * AROW + koff + lh * 32;
            pw = wrowMain + c * 64;
        } else {
            int koff = (c - NWCH) << 6;
            pa = xrow + koff;
            pw = wrowSC + koff;
        }
        #pragma unroll
        for (int j = 0; j < 4; ++j) {
            CP_ASYNC16(bufbase + soA[j], (const char*)pa + j * 16);
            CP_ASYNC16(bufbase + soB[j], (const char*)pw + j * 16);
        }
    };

    issue_load(0, sb32 + SM_BUF);
    CP_COMMIT();
    issue_load(1, sb32 + SM_BUF + BUFSZ);
    CP_COMMIT();

    // ---- hoisted ldmatrix addressing (all fragment rows have row&7 == lane&7) ----
    int sx = lane & 7;
    int abit = lane >> 4;
    int bbit = (lane >> 3) & 1;
    uint32_t arow0 = OFF_A + (uint32_t)(wm * 64 + (lane & 15)) * 128;
    uint32_t brow0 = OFF_B + (uint32_t)(wn * 32 + ((lane >> 4) << 3) + sx) * 128;
    uint32_t kA[4], kB[4];
    #pragma unroll
    for (int s = 0; s < 4; ++s) {
        kA[s] = (uint32_t)(((2 * s + abit) ^ sx) << 4);
        kB[s] = (uint32_t)(((2 * s + bbit) ^ sx) << 4);
    }

    float acc[4][4][4];
    #pragma unroll
    for (int i = 0; i < 4; ++i)
        #pragma unroll
        for (int j = 0; j < 4; ++j)
            #pragma unroll
            for (int k = 0; k < 4; ++k) acc[i][j][k] = 0.f;

    int st = 0;                 // = c % 3
    int st2 = 2;                // = (c + 2) % 3
    for (int c = 0; c < NC; ++c) {
        if (c + 2 < NC) { CP_WAIT1(); } else { CP_WAIT0(); }
        __syncthreads();        // stage c ready; stage st2 reads done by all

        if (c + 2 < NC) {
            issue_load(c + 2, sb32 + SM_BUF + st2 * BUFSZ);
            CP_COMMIT();
        }

        uint32_t base = sb32 + SM_BUF + st * BUFSZ;
        uint32_t aaddr = base + arow0;
        uint32_t baddr = base + brow0;
        #pragma unroll
        for (int s = 0; s < 4; ++s) {
            uint32_t af[4][4], bhf[4][2];
            #pragma unroll
            for (int i = 0; i < 4; ++i)
                LDSM4(af[i][0], af[i][1], af[i][2], af[i][3],
                      aaddr + (uint32_t)(i * 2048) + kA[s]);
            #pragma unroll
            for (int p = 0; p < 2; ++p) {
                uint32_t t0, t1, t2, t3;
                LDSM4(t0, t1, t2, t3, baddr + (uint32_t)(p * 2048) + kB[s]);
                bhf[2*p][0] = t0; bhf[2*p][1] = t1; bhf[2*p+1][0] = t2; bhf[2*p+1][1] = t3;
            }
            #pragma unroll
            for (int i = 0; i < 4; ++i)
                #pragma unroll
                for (int j = 0; j < 4; ++j) MMA_F16(acc[i][j], af[i], bhf[j]);
        }
        st  = (st  == 2) ? 0 : st  + 1;
        st2 = (st2 == 2) ? 0 : st2 + 1;
    }

    // ---- epilogue ----
    int lr = lane >> 2;
    int lc = (lane & 3) * 2;
    #pragma unroll
    for (int j = 0; j < 4; ++j) {
        int col = colB + wn * 32 + j * 8 + lc;
        float ax = bias[col]     + (CONV2 ? bias2[col]     : g_t[b * COUTD + col]);
        float ay = bias[col + 1] + (CONV2 ? bias2[col + 1] : g_t[b * COUTD + col + 1]);
        float sj = 0.f, qj = 0.f;
        #pragma unroll
        for (int i = 0; i < 4; ++i) {
            int r0 = rowStart + wm * 64 + i * 16 + lr;
            float o0 = acc[i][j][0] + ax, o1 = acc[i][j][1] + ay;
            float o2 = acc[i][j][2] + ax, o3 = acc[i][j][3] + ay;
            if (CONV2) {
                float2 v0 = {o0, o1}, v1 = {o2, o3};
                *reinterpret_cast<float2*>(&outp[(size_t)r0 * COUTD + col]) = v0;
                *reinterpret_cast<float2*>(&outp[(size_t)(r0 + 8) * COUTD + col]) = v1;
            } else {
                __half2 p0 = __floats2half2_rn(o0, o1);
                __half2 p1 = __floats2half2_rn(o2, o3);
                *reinterpret_cast<__half2*>(&g_h16[(size_t)r0 * COUTD + col]) = p0;
                *reinterpret_cast<__half2*>(&g_h16[(size_t)(r0 + 8) * COUTD + col]) = p1;
                sj += o0 + o1 + o2 + o3;
                qj += o0 * o0 + o1 * o1 + o2 * o2 + o3 * o3;
            }
        }
        if (!CONV2) {
            #pragma unroll
            for (int off = 16; off; off >>= 1) {
                sj += __shfl_xor_sync(0xFFFFFFFFu, sj, off);
                qj += __shfl_xor_sync(0xFFFFFFFFu, qj, off);
            }
            if (lane == 0) {
                atomicAdd(&sg[wn * 4 + j], sj);
                atomicAdd(&sq[wn * 4 + j], qj);
            }
        }
    }
    if (!CONV2) {
        __syncthreads();
        if (tid < 16) {
            int gidx = b * 32 + (colB >> 3) + tid;
            atomicAdd(&g_sum2[gidx], sg[tid]);
            atomicAdd(&g_sumsq2[gidx], sq[tid]);
        }
    }
}

// ================= launch =================
extern "C" void kernel_launch(void* const* d_in, const int* in_sizes, int n_in,
                              void* d_out, int out_size) {
    const float* x      = (const float*)d_in[0];
    const float* t_emb  = (const float*)d_in[1];
    const int*   neigh  = (const int*)d_in[2];
    const float* gn1_w  = (const float*)d_in[3];
    const float* gn1_b  = (const float*)d_in[4];
    const float* w1     = (const float*)d_in[5];
    const float* b1     = (const float*)d_in[6];
    const float* wt     = (const float*)d_in[7];
    const float* bt     = (const float*)d_in[8];
    const float* gn2_w  = (const float*)d_in[9];
    const float* gn2_b  = (const float*)d_in[10];
    const float* w2     = (const float*)d_in[11];
    const float* b2     = (const float*)d_in[12];
    const float* ws     = (const float*)d_in[13];
    const float* bs     = (const float*)d_in[14];
    float* out = (float*)d_out;

    static bool attr_set = false;
    if (!attr_set) {
        cudaFuncSetAttribute(conv_mma_kernel<false>, cudaFuncAttributeMaxDynamicSharedMemorySize, SMEMSZ);
        cudaFuncSetAttribute(conv_mma_kernel<true>,  cudaFuncAttributeMaxDynamicSharedMemorySize, SMEMSZ);
        attr_set = true;
    }

    prep_kernel<<<3601, 256>>>(t_emb, wt, bt, w1, w2, ws);
    gn1_stats_kernel<<<1024, 256>>>(x);
    hn1split_kernel<<<16384, 256>>>(x, gn1_w, gn1_b);
    conv_mma_kernel<false><<<dim3(1024, 2), 256, SMEMSZ>>>(b1, nullptr, neigh, nullptr);
    hn2split_kernel<<<32768, 256>>>(gn2_w, gn2_b);
    conv_mma_kernel<true><<<dim3(1024, 2), 256, SMEMSZ>>>(b2, bs, neigh, out);
}